// round 1
// baseline (speedup 1.0000x reference)
#include <cuda_runtime.h>
#include <math.h>

#define N_NODES 100000
#define D_FEAT  128
#define HIDDEN  128

// Scratch: per-node projections A = x @ W1[:128], B = x @ W1[128:]
__device__ float g_A[N_NODES * HIDDEN];
__device__ float g_B[N_NODES * HIDDEN];

// ---------------------------------------------------------------------------
// Stage 1: node GEMM.  C[100000, 256] = X[100000, 128] @ W[128, 256]
// where W[k][j] = W1[k][j] for j<128 (A-half), W1[128+k][j-128] for j>=128 (B).
// Block: 256 threads, tile 64 nodes x 256 outputs, 8x8 microtile per thread.
// X tile transposed in smem (stride 68 to dodge bank conflicts, float4-aligned);
// W streamed through L1 (reused across the 8 m-groups within each warp).
// ---------------------------------------------------------------------------
__global__ __launch_bounds__(256) void node_gemm_kernel(
    const float* __restrict__ x,
    const float* __restrict__ W1)
{
    __shared__ float sX[128 * 68];   // [k][m], padded

    const int m_block = blockIdx.x * 64;
    const int tid = threadIdx.x;

    // Load + transpose X tile: sX[k][m] = x[m_block+m][k]
    #pragma unroll
    for (int i = tid; i < 64 * 128; i += 256) {
        int m = i >> 7;
        int k = i & 127;
        int gm = m_block + m;
        float v = (gm < N_NODES) ? x[gm * D_FEAT + k] : 0.0f;
        sX[k * 68 + m] = v;
    }
    __syncthreads();

    const int nt = tid & 31;   // output-col group
    const int mt = tid >> 5;   // node group
    const int n0 = nt * 8;     // 0..248
    const int m0 = mt * 8;     // 0..56

    // Column base into W1, folding the A/B half selection.
    const float* wbase = (n0 < 128) ? (W1 + n0)
                                    : (W1 + 128 * HIDDEN + (n0 - 128));

    float acc[8][8];
    #pragma unroll
    for (int i = 0; i < 8; i++)
        #pragma unroll
        for (int j = 0; j < 8; j++) acc[i][j] = 0.0f;

    #pragma unroll 4
    for (int k = 0; k < 128; k++) {
        float4 xa = *(const float4*)&sX[k * 68 + m0];
        float4 xb = *(const float4*)&sX[k * 68 + m0 + 4];
        float4 wa = *(const float4*)&wbase[k * HIDDEN];
        float4 wb = *(const float4*)&wbase[k * HIDDEN + 4];
        float xm[8] = {xa.x, xa.y, xa.z, xa.w, xb.x, xb.y, xb.z, xb.w};
        float wn[8] = {wa.x, wa.y, wa.z, wa.w, wb.x, wb.y, wb.z, wb.w};
        #pragma unroll
        for (int im = 0; im < 8; im++)
            #pragma unroll
            for (int jn = 0; jn < 8; jn++)
                acc[im][jn] = fmaf(xm[im], wn[jn], acc[im][jn]);
    }

    // Store 8 nodes x 8 cols (cols entirely within A-half or B-half).
    #pragma unroll
    for (int im = 0; im < 8; im++) {
        int gm = m_block + m0 + im;
        if (gm >= N_NODES) continue;
        float* dst = (n0 < 128) ? (g_A + gm * HIDDEN + n0)
                                : (g_B + gm * HIDDEN + (n0 - 128));
        *(float4*)dst       = make_float4(acc[im][0], acc[im][1], acc[im][2], acc[im][3]);
        *(float4*)(dst + 4) = make_float4(acc[im][4], acc[im][5], acc[im][6], acc[im][7]);
    }
}

// ---------------------------------------------------------------------------
// Stage 2: per-edge. One warp per edge.
//   h = tanh(A[src] + B[dst] + b1);  out = sigmoid(h . W2 + b2)
// Index dtype (int32 vs int64) detected at runtime: for int64 data the odd
// 32-bit words are all zero (values < 2^31).
// ---------------------------------------------------------------------------
__global__ __launch_bounds__(256) void edge_kernel(
    const void*  __restrict__ idx,
    const float* __restrict__ b1,
    const float* __restrict__ W2,
    const float* __restrict__ b2,
    float*       __restrict__ out,
    int E)
{
    const int warp = (int)((blockIdx.x * blockDim.x + threadIdx.x) >> 5);
    const int lane = threadIdx.x & 31;
    if (warp >= E) return;

    const int* w32 = (const int*)idx;
    const bool is64 = ((w32[1] | w32[3] | w32[5] | w32[7]) == 0);

    int s, d;
    if (is64) {
        const long long* p = (const long long*)idx;
        s = (int)p[warp];
        d = (int)p[E + warp];
    } else {
        s = w32[warp];
        d = w32[E + warp];
    }

    const int j = lane * 4;
    float4 a  = *(const float4*)&g_A[s * HIDDEN + j];
    float4 b  = *(const float4*)&g_B[d * HIDDEN + j];
    float4 bb = *(const float4*)&b1[j];
    float4 w  = *(const float4*)&W2[j];

    float h0 = tanhf(a.x + b.x + bb.x);
    float h1 = tanhf(a.y + b.y + bb.y);
    float h2 = tanhf(a.z + b.z + bb.z);
    float h3 = tanhf(a.w + b.w + bb.w);

    float p = h0 * w.x + h1 * w.y + h2 * w.z + h3 * w.w;

    #pragma unroll
    for (int off = 16; off; off >>= 1)
        p += __shfl_xor_sync(0xffffffffu, p, off);

    if (lane == 0) {
        float logit = p + b2[0];
        out[warp] = 1.0f / (1.0f + __expf(-logit));
    }
}

// ---------------------------------------------------------------------------
extern "C" void kernel_launch(void* const* d_in, const int* in_sizes, int n_in,
                              void* d_out, int out_size)
{
    const float* x   = (const float*)d_in[0];
    const void*  idx = d_in[1];
    const float* W1  = (const float*)d_in[2];
    const float* b1  = (const float*)d_in[3];
    const float* W2  = (const float*)d_in[4];
    const float* b2  = (const float*)d_in[5];
    float* out = (float*)d_out;

    const int E = in_sizes[1] / 2;

    // Stage 1: 1563 blocks of 256 threads, 64 nodes each.
    const int n_blocks1 = (N_NODES + 63) / 64;
    node_gemm_kernel<<<n_blocks1, 256>>>(x, W1);

    // Stage 2: one warp per edge, 8 warps per block.
    const int n_blocks2 = (E + 7) / 8;
    edge_kernel<<<n_blocks2, 256>>>(idx, b1, W2, b2, out, E);
}

// round 3
// speedup vs baseline: 1.3723x; 1.3723x over previous
#include <cuda_runtime.h>
#include <cuda_bf16.h>
#include <cstdint>

#define N_NODES 100000
#define D_FEAT  128
#define HIDDEN  128
#define M_TILE  128
#define KPAD    136          // bf16 row stride (272 B) -> conflict-free fragment loads

// ---------------------------------------------------------------------------
// Global scratch
// ---------------------------------------------------------------------------
__device__ float g_A[N_NODES * HIDDEN];            // x @ W1[:128] + b1
__device__ float g_B[N_NODES * HIDDEN];            // x @ W1[128:]
__device__ __nv_bfloat16 g_Whi[256 * KPAD];        // Wfull^T padded, hi part
__device__ __nv_bfloat16 g_Wlo[256 * KPAD];        // lo part

// ---------------------------------------------------------------------------
// Prep: Wfull[k][n] (256 cols n) -> g_W{hi,lo}[n][k], bf16 split.
// ---------------------------------------------------------------------------
__global__ __launch_bounds__(256) void prep_w_kernel(const float* __restrict__ W1)
{
    int i = blockIdx.x * 256 + threadIdx.x;        // n*128 + k
    if (i >= 256 * 128) return;
    int n = i >> 7, k = i & 127;
    // Wfull[k][n]: n<128 -> W1[k][n]; n>=128 -> W1[128+k][n-128]
    int r = (n < 128) ? k : (128 + k);
    int c = (n < 128) ? n : (n - 128);
    float v = W1[r * 128 + c];
    __nv_bfloat16 hv = __float2bfloat16(v);
    __nv_bfloat16 lv = __float2bfloat16(v - __bfloat162float(hv));
    g_Whi[n * KPAD + k] = hv;
    g_Wlo[n * KPAD + k] = lv;
}

// ---------------------------------------------------------------------------
// Stage 1: C[128 nodes][128 cols] per CTA via mma.sync m16n8k16 bf16.
// grid.x = m-tiles (782), grid.y = 2 (col half: 0 -> g_A(+b1), 1 -> g_B).
// 3 accumulation passes: Xhi*Whi, Xhi*Wlo, Xlo*Whi.
// SMEM: sXhi, sXlo, sWhi, sWlo each [128][KPAD] bf16 = 34816 B. Total 139264 B.
// ---------------------------------------------------------------------------
#define SM_XHI 0
#define SM_XLO 34816
#define SM_WHI 69632
#define SM_WLO 104448
#define SMEM_TOTAL 139264

static __device__ __forceinline__ void mma_bf16(
    float c[4], const uint32_t a[4], const uint32_t b[2])
{
    asm volatile(
        "mma.sync.aligned.m16n8k16.row.col.f32.bf16.bf16.f32 "
        "{%0,%1,%2,%3}, {%4,%5,%6,%7}, {%8,%9}, {%0,%1,%2,%3};"
        : "+f"(c[0]), "+f"(c[1]), "+f"(c[2]), "+f"(c[3])
        : "r"(a[0]), "r"(a[1]), "r"(a[2]), "r"(a[3]), "r"(b[0]), "r"(b[1]));
}

__global__ __launch_bounds__(256) void node_gemm_kernel(
    const float* __restrict__ x,
    const float* __restrict__ b1)
{
    extern __shared__ char smem[];
    __nv_bfloat16* sXhi = (__nv_bfloat16*)(smem + SM_XHI);
    __nv_bfloat16* sXlo = (__nv_bfloat16*)(smem + SM_XLO);
    __nv_bfloat16* sWhi = (__nv_bfloat16*)(smem + SM_WHI);
    __nv_bfloat16* sWlo = (__nv_bfloat16*)(smem + SM_WLO);

    const int tid     = threadIdx.x;
    const int m_block = blockIdx.x * M_TILE;
    const int nhalf   = blockIdx.y;            // 0: A-half, 1: B-half

    // ---- load X tile (128 x 128 fp32), split to bf16 hi/lo
    for (int i = tid; i < M_TILE * 64; i += 256) {
        int m = i >> 6;
        int k = (i & 63) * 2;
        int gm = m_block + m;
        float2 v = make_float2(0.f, 0.f);
        if (gm < N_NODES) v = *(const float2*)&x[gm * D_FEAT + k];
        __nv_bfloat16 h0 = __float2bfloat16(v.x);
        __nv_bfloat16 h1 = __float2bfloat16(v.y);
        __nv_bfloat16 l0 = __float2bfloat16(v.x - __bfloat162float(h0));
        __nv_bfloat16 l1 = __float2bfloat16(v.y - __bfloat162float(h1));
        *(uint32_t*)&sXhi[m * KPAD + k] =
            ((uint32_t)__bfloat16_as_ushort(h1) << 16) | __bfloat16_as_ushort(h0);
        *(uint32_t*)&sXlo[m * KPAD + k] =
            ((uint32_t)__bfloat16_as_ushort(l1) << 16) | __bfloat16_as_ushort(l0);
    }
    // ---- copy this half's W images (128 rows x KPAD), linear 8B chunks
    {
        const uint2* ghi = (const uint2*)(g_Whi + nhalf * 128 * KPAD);
        const uint2* glo = (const uint2*)(g_Wlo + nhalf * 128 * KPAD);
        uint2* shi = (uint2*)sWhi;
        uint2* slo = (uint2*)sWlo;
        for (int i = tid; i < 128 * KPAD / 4; i += 256) {
            shi[i] = ghi[i];
            slo[i] = glo[i];
        }
    }
    __syncthreads();

    // ---- warp tiling: 8 warps, each 32(M) x 64(N)
    const int wid  = tid >> 5;
    const int lane = tid & 31;
    const int g    = lane >> 2;        // group id (row within 8)
    const int t    = lane & 3;         // thread in group
    const int mrow0 = (wid & 3) * 32;
    const int ncol0 = (wid >> 2) * 64;

    float acc[2][8][4];
    #pragma unroll
    for (int mt = 0; mt < 2; mt++)
        #pragma unroll
        for (int nt = 0; nt < 8; nt++)
            #pragma unroll
            for (int r = 0; r < 4; r++) acc[mt][nt][r] = 0.f;

    #pragma unroll
    for (int pass = 0; pass < 3; pass++) {
        const __nv_bfloat16* sX = (pass == 2) ? sXlo : sXhi;
        const __nv_bfloat16* sW = (pass == 1) ? sWlo : sWhi;
        #pragma unroll
        for (int ks = 0; ks < 8; ks++) {
            const int k0 = ks * 16;
            uint32_t a[2][4];
            #pragma unroll
            for (int mt = 0; mt < 2; mt++) {
                const int rb = mrow0 + mt * 16;
                a[mt][0] = *(const uint32_t*)&sX[(rb + g)     * KPAD + k0 + t * 2];
                a[mt][1] = *(const uint32_t*)&sX[(rb + g + 8) * KPAD + k0 + t * 2];
                a[mt][2] = *(const uint32_t*)&sX[(rb + g)     * KPAD + k0 + t * 2 + 8];
                a[mt][3] = *(const uint32_t*)&sX[(rb + g + 8) * KPAD + k0 + t * 2 + 8];
            }
            #pragma unroll
            for (int nt = 0; nt < 8; nt++) {
                const int cb = ncol0 + nt * 8;
                uint32_t b[2];
                b[0] = *(const uint32_t*)&sW[(cb + g) * KPAD + k0 + t * 2];
                b[1] = *(const uint32_t*)&sW[(cb + g) * KPAD + k0 + t * 2 + 8];
                mma_bf16(acc[0][nt], a[0], b);
                mma_bf16(acc[1][nt], a[1], b);
            }
        }
    }

    // ---- epilogue: add b1 (A-half only), store float2 pairs
    float2 bb[8];
    #pragma unroll
    for (int nt = 0; nt < 8; nt++) {
        if (nhalf == 0) bb[nt] = *(const float2*)&b1[ncol0 + nt * 8 + t * 2];
        else            bb[nt] = make_float2(0.f, 0.f);
    }
    float* halfp = nhalf ? g_B : g_A;
    #pragma unroll
    for (int mt = 0; mt < 2; mt++) {
        const int node0 = m_block + mrow0 + mt * 16 + g;
        const int node1 = node0 + 8;
        #pragma unroll
        for (int nt = 0; nt < 8; nt++) {
            const int c = ncol0 + nt * 8 + t * 2;
            if (node0 < N_NODES)
                *(float2*)&halfp[(size_t)node0 * HIDDEN + c] =
                    make_float2(acc[mt][nt][0] + bb[nt].x, acc[mt][nt][1] + bb[nt].y);
            if (node1 < N_NODES)
                *(float2*)&halfp[(size_t)node1 * HIDDEN + c] =
                    make_float2(acc[mt][nt][2] + bb[nt].x, acc[mt][nt][3] + bb[nt].y);
        }
    }
}

// ---------------------------------------------------------------------------
// Stage 2: persistent warp-per-edge-pair.
//   out[e] = sigmoid( dot(tanh(A[src] + B[dst]), W2) + b2 )   (b1 folded in A)
// ---------------------------------------------------------------------------
static __device__ __forceinline__ float tanh_fast(float x) {
    float y;
    asm("tanh.approx.f32 %0, %1;" : "=f"(y) : "f"(x));
    return y;
}

__global__ __launch_bounds__(256) void edge_kernel(
    const void*  __restrict__ idx,
    const float* __restrict__ W2,
    const float* __restrict__ b2,
    float*       __restrict__ out,
    int E)
{
    const int lane = threadIdx.x & 31;
    const int gwarp = (blockIdx.x * blockDim.x + threadIdx.x) >> 5;
    const int nwarps = (gridDim.x * blockDim.x) >> 5;

    const int* w32 = (const int*)idx;
    const bool is64 = ((w32[1] | w32[3] | w32[5] | w32[7]) == 0);
    const long long* p64 = (const long long*)idx;

    const int j = lane * 4;
    const float4 w = *(const float4*)&W2[j];
    const float bias2 = b2[0];

    const int P = (E + 1) >> 1;
    for (int p = gwarp; p < P; p += nwarps) {
        int e0 = p * 2, e1 = e0 + 1;
        int s0, d0, s1, d1;
        if (is64) {
            s0 = (int)p64[e0];      d0 = (int)p64[E + e0];
            s1 = (e1 < E) ? (int)p64[e1] : s0;
            d1 = (e1 < E) ? (int)p64[E + e1] : d0;
        } else {
            s0 = w32[e0];           d0 = w32[E + e0];
            s1 = (e1 < E) ? w32[e1] : s0;
            d1 = (e1 < E) ? w32[E + e1] : d0;
        }

        float4 a0  = *(const float4*)&g_A[(size_t)s0 * HIDDEN + j];
        float4 b0  = *(const float4*)&g_B[(size_t)d0 * HIDDEN + j];
        float4 a1  = *(const float4*)&g_A[(size_t)s1 * HIDDEN + j];
        float4 b1v = *(const float4*)&g_B[(size_t)d1 * HIDDEN + j];

        float acc0 = tanh_fast(a0.x + b0.x) * w.x;
        acc0 = fmaf(tanh_fast(a0.y + b0.y), w.y, acc0);
        acc0 = fmaf(tanh_fast(a0.z + b0.z), w.z, acc0);
        acc0 = fmaf(tanh_fast(a0.w + b0.w), w.w, acc0);

        float acc1 = tanh_fast(a1.x + b1v.x) * w.x;
        acc1 = fmaf(tanh_fast(a1.y + b1v.y), w.y, acc1);
        acc1 = fmaf(tanh_fast(a1.z + b1v.z), w.z, acc1);
        acc1 = fmaf(tanh_fast(a1.w + b1v.w), w.w, acc1);

        #pragma unroll
        for (int off = 16; off; off >>= 1) {
            acc0 += __shfl_xor_sync(0xffffffffu, acc0, off);
            acc1 += __shfl_xor_sync(0xffffffffu, acc1, off);
        }

        if (lane == 0) {
            out[e0] = __fdividef(1.0f, 1.0f + __expf(-(acc0 + bias2)));
        } else if (lane == 1 && e1 < E) {
            out[e1] = __fdividef(1.0f, 1.0f + __expf(-(acc1 + bias2)));
        }
    }
}

// ---------------------------------------------------------------------------
extern "C" void kernel_launch(void* const* d_in, const int* in_sizes, int n_in,
                              void* d_out, int out_size)
{
    const float* x   = (const float*)d_in[0];
    const void*  idx = d_in[1];
    const float* W1  = (const float*)d_in[2];
    const float* b1  = (const float*)d_in[3];
    const float* W2  = (const float*)d_in[4];
    const float* b2  = (const float*)d_in[5];
    float* out = (float*)d_out;

    const int E = in_sizes[1] / 2;

    cudaFuncSetAttribute(node_gemm_kernel,
                         cudaFuncAttributeMaxDynamicSharedMemorySize, SMEM_TOTAL);

    prep_w_kernel<<<128, 256>>>(W1);

    dim3 grid1((N_NODES + M_TILE - 1) / M_TILE, 2);    // 782 x 2
    node_gemm_kernel<<<grid1, 256, SMEM_TOTAL>>>(x, b1);

    edge_kernel<<<1184, 256>>>(idx, W2, b2, out, E);
}

// round 4
// speedup vs baseline: 1.4861x; 1.0830x over previous
#include <cuda_runtime.h>
#include <cuda_bf16.h>
#include <cuda_fp16.h>
#include <cstdint>

#define N_NODES 100000
#define D_FEAT  128
#define HIDDEN  128
#define M_TILE  128
#define KPAD    136          // bf16 row stride (272 B) -> conflict-free fragment loads

// ---------------------------------------------------------------------------
// Global scratch.  A/B stored as fp16: halves gather traffic, 51 MB working
// set -> fully L2-resident for the edge stage.
// ---------------------------------------------------------------------------
__device__ __half g_A[N_NODES * HIDDEN];           // x @ W1[:128] + b1
__device__ __half g_B[N_NODES * HIDDEN];           // x @ W1[128:]
__device__ __nv_bfloat16 g_Whi[256 * KPAD];        // Wfull^T padded, hi part
__device__ __nv_bfloat16 g_Wlo[256 * KPAD];        // lo part

// ---------------------------------------------------------------------------
// Prep: Wfull[k][n] (256 cols n) -> g_W{hi,lo}[n][k], bf16 split.
// ---------------------------------------------------------------------------
__global__ __launch_bounds__(256) void prep_w_kernel(const float* __restrict__ W1)
{
    int i = blockIdx.x * 256 + threadIdx.x;        // n*128 + k
    if (i >= 256 * 128) return;
    int n = i >> 7, k = i & 127;
    int r = (n < 128) ? k : (128 + k);
    int c = (n < 128) ? n : (n - 128);
    float v = W1[r * 128 + c];
    __nv_bfloat16 hv = __float2bfloat16(v);
    __nv_bfloat16 lv = __float2bfloat16(v - __bfloat162float(hv));
    g_Whi[n * KPAD + k] = hv;
    g_Wlo[n * KPAD + k] = lv;
}

// ---------------------------------------------------------------------------
// Stage 1: C[128 nodes][256 cols] per CTA via mma.sync m16n8k16 bf16.
// 512 threads, 16 warps in a 4x4 grid of 32(M) x 64(N) warp tiles.
// 3 accumulation passes: Xhi*Whi, Xhi*Wlo, Xlo*Whi.
// SMEM: sXhi/sXlo [128][KPAD], sWhi/sWlo [256][KPAD]. Total 208896 B.
// ---------------------------------------------------------------------------
#define SM_XHI 0
#define SM_XLO 34816
#define SM_WHI 69632
#define SM_WLO 139264
#define SMEM_TOTAL 208896

static __device__ __forceinline__ uint32_t smem_u32(const void* p) {
    uint32_t a;
    asm("{ .reg .u64 t; cvta.to.shared.u64 t, %1; cvt.u32.u64 %0, t; }" : "=r"(a) : "l"(p));
    return a;
}

static __device__ __forceinline__ void mma_bf16(
    float c[4], const uint32_t a[4], const uint32_t b[2])
{
    asm volatile(
        "mma.sync.aligned.m16n8k16.row.col.f32.bf16.bf16.f32 "
        "{%0,%1,%2,%3}, {%4,%5,%6,%7}, {%8,%9}, {%0,%1,%2,%3};"
        : "+f"(c[0]), "+f"(c[1]), "+f"(c[2]), "+f"(c[3])
        : "r"(a[0]), "r"(a[1]), "r"(a[2]), "r"(a[3]), "r"(b[0]), "r"(b[1]));
}

__global__ __launch_bounds__(512) void node_gemm_kernel(
    const float* __restrict__ x,
    const float* __restrict__ b1)
{
    extern __shared__ char smem[];
    __nv_bfloat16* sXhi = (__nv_bfloat16*)(smem + SM_XHI);
    __nv_bfloat16* sXlo = (__nv_bfloat16*)(smem + SM_XLO);
    __nv_bfloat16* sWhi = (__nv_bfloat16*)(smem + SM_WHI);
    __nv_bfloat16* sWlo = (__nv_bfloat16*)(smem + SM_WLO);

    const int tid     = threadIdx.x;
    const int m_block = blockIdx.x * M_TILE;

    // ---- kick off W copy with cp.async (overlaps with X load+convert below)
    {
        const uint32_t shi = smem_u32(sWhi);
        const uint32_t slo = smem_u32(sWlo);
        const char* ghi = (const char*)g_Whi;
        const char* glo = (const char*)g_Wlo;
        for (int i = tid * 16; i < 256 * KPAD * 2; i += 512 * 16) {
            asm volatile("cp.async.cg.shared.global [%0], [%1], 16;"
                         :: "r"(shi + i), "l"(ghi + i));
            asm volatile("cp.async.cg.shared.global [%0], [%1], 16;"
                         :: "r"(slo + i), "l"(glo + i));
        }
        asm volatile("cp.async.commit_group;");
    }

    // ---- load X tile (128 x 128 fp32), split to bf16 hi/lo
    for (int i = tid; i < M_TILE * 64; i += 512) {
        int m = i >> 6;
        int k = (i & 63) * 2;
        int gm = m_block + m;
        float2 v = make_float2(0.f, 0.f);
        if (gm < N_NODES) v = *(const float2*)&x[gm * D_FEAT + k];
        __nv_bfloat16 h0 = __float2bfloat16(v.x);
        __nv_bfloat16 h1 = __float2bfloat16(v.y);
        __nv_bfloat16 l0 = __float2bfloat16(v.x - __bfloat162float(h0));
        __nv_bfloat16 l1 = __float2bfloat16(v.y - __bfloat162float(h1));
        *(uint32_t*)&sXhi[m * KPAD + k] =
            ((uint32_t)__bfloat16_as_ushort(h1) << 16) | __bfloat16_as_ushort(h0);
        *(uint32_t*)&sXlo[m * KPAD + k] =
            ((uint32_t)__bfloat16_as_ushort(l1) << 16) | __bfloat16_as_ushort(l0);
    }
    asm volatile("cp.async.wait_group 0;");
    __syncthreads();

    // ---- warp tiling: 16 warps, each 32(M) x 64(N)
    const int wid  = tid >> 5;
    const int lane = tid & 31;
    const int g    = lane >> 2;
    const int t    = lane & 3;
    const int mrow0 = (wid & 3) * 32;
    const int ncol0 = (wid >> 2) * 64;     // 0,64,128,192

    float acc[2][8][4];
    #pragma unroll
    for (int mt = 0; mt < 2; mt++)
        #pragma unroll
        for (int nt = 0; nt < 8; nt++)
            #pragma unroll
            for (int r = 0; r < 4; r++) acc[mt][nt][r] = 0.f;

    #pragma unroll
    for (int pass = 0; pass < 3; pass++) {
        const __nv_bfloat16* sX = (pass == 2) ? sXlo : sXhi;
        const __nv_bfloat16* sW = (pass == 1) ? sWlo : sWhi;
        #pragma unroll
        for (int ks = 0; ks < 8; ks++) {
            const int k0 = ks * 16;
            uint32_t a[2][4];
            #pragma unroll
            for (int mt = 0; mt < 2; mt++) {
                const int rb = mrow0 + mt * 16;
                a[mt][0] = *(const uint32_t*)&sX[(rb + g)     * KPAD + k0 + t * 2];
                a[mt][1] = *(const uint32_t*)&sX[(rb + g + 8) * KPAD + k0 + t * 2];
                a[mt][2] = *(const uint32_t*)&sX[(rb + g)     * KPAD + k0 + t * 2 + 8];
                a[mt][3] = *(const uint32_t*)&sX[(rb + g + 8) * KPAD + k0 + t * 2 + 8];
            }
            #pragma unroll
            for (int nt = 0; nt < 8; nt++) {
                const int cb = ncol0 + nt * 8;
                uint32_t b[2];
                b[0] = *(const uint32_t*)&sW[(cb + g) * KPAD + k0 + t * 2];
                b[1] = *(const uint32_t*)&sW[(cb + g) * KPAD + k0 + t * 2 + 8];
                mma_bf16(acc[0][nt], a[0], b);
                mma_bf16(acc[1][nt], a[1], b);
            }
        }
    }

    // ---- epilogue: +b1 for A-half cols, convert to fp16, store half2
    const bool isA = (ncol0 < 128);
    __half* halfp = isA ? g_A : g_B;
    const int clocal0 = isA ? ncol0 : (ncol0 - 128);

    float2 bb[8];
    #pragma unroll
    for (int nt = 0; nt < 8; nt++) {
        if (isA) bb[nt] = *(const float2*)&b1[ncol0 + nt * 8 + t * 2];
        else     bb[nt] = make_float2(0.f, 0.f);
    }
    #pragma unroll
    for (int mt = 0; mt < 2; mt++) {
        const int node0 = m_block + mrow0 + mt * 16 + g;
        const int node1 = node0 + 8;
        #pragma unroll
        for (int nt = 0; nt < 8; nt++) {
            const int c = clocal0 + nt * 8 + t * 2;
            if (node0 < N_NODES)
                *(__half2*)&halfp[(size_t)node0 * HIDDEN + c] =
                    __floats2half2_rn(acc[mt][nt][0] + bb[nt].x, acc[mt][nt][1] + bb[nt].y);
            if (node1 < N_NODES)
                *(__half2*)&halfp[(size_t)node1 * HIDDEN + c] =
                    __floats2half2_rn(acc[mt][nt][2] + bb[nt].x, acc[mt][nt][3] + bb[nt].y);
        }
    }
}

// ---------------------------------------------------------------------------
// Stage 2: half-warp per edge.  Each 16-lane half loads one edge's A row
// (256 B, one uint4 per lane) + B row, computes 8 tanh terms per lane,
// reduces in 4 shuffle steps.
// ---------------------------------------------------------------------------
static __device__ __forceinline__ float tanh_fast(float x) {
    float y;
    asm("tanh.approx.f32 %0, %1;" : "=f"(y) : "f"(x));
    return y;
}

__global__ __launch_bounds__(256) void edge_kernel(
    const void*  __restrict__ idx,
    const float* __restrict__ W2,
    const float* __restrict__ b2,
    float*       __restrict__ out,
    int E)
{
    const int lane = threadIdx.x & 31;
    const int hw   = lane >> 4;            // which half-warp
    const int hl   = lane & 15;            // lane within half
    const int gwarp = (blockIdx.x * blockDim.x + threadIdx.x) >> 5;
    const int nwarps = (gridDim.x * blockDim.x) >> 5;

    const int* w32 = (const int*)idx;
    const bool is64 = ((w32[1] | w32[3] | w32[5] | w32[7]) == 0);
    const long long* p64 = (const long long*)idx;

    float wv[8];
    {
        float4 w0 = *(const float4*)&W2[hl * 8];
        float4 w1 = *(const float4*)&W2[hl * 8 + 4];
        wv[0] = w0.x; wv[1] = w0.y; wv[2] = w0.z; wv[3] = w0.w;
        wv[4] = w1.x; wv[5] = w1.y; wv[6] = w1.z; wv[7] = w1.w;
    }
    const float bias2 = b2[0];

    const uint4* Au = (const uint4*)g_A;   // 16 uint4 per row
    const uint4* Bu = (const uint4*)g_B;

    const int P = (E + 1) >> 1;
    for (int p = gwarp; p < P; p += nwarps) {
        const int e = p * 2 + hw;
        const bool valid = (e < E);
        const int ec = valid ? e : (E - 1);

        int s, d;
        if (is64) { s = (int)p64[ec]; d = (int)p64[E + ec]; }
        else      { s = w32[ec];      d = w32[E + ec]; }

        uint4 ua = Au[(size_t)s * 16 + hl];
        uint4 ub = Bu[(size_t)d * 16 + hl];

        float acc = 0.f;
        {
            const uint32_t* pa = (const uint32_t*)&ua;
            const uint32_t* pb = (const uint32_t*)&ub;
            #pragma unroll
            for (int q = 0; q < 4; q++) {
                float2 af = __half22float2(*(const __half2*)&pa[q]);
                float2 bf = __half22float2(*(const __half2*)&pb[q]);
                acc = fmaf(tanh_fast(af.x + bf.x), wv[q * 2],     acc);
                acc = fmaf(tanh_fast(af.y + bf.y), wv[q * 2 + 1], acc);
            }
        }

        #pragma unroll
        for (int off = 8; off; off >>= 1)
            acc += __shfl_xor_sync(0xffffffffu, acc, off);

        if (hl == 0 && valid)
            out[e] = __fdividef(1.0f, 1.0f + __expf(-(acc + bias2)));
    }
}

// ---------------------------------------------------------------------------
extern "C" void kernel_launch(void* const* d_in, const int* in_sizes, int n_in,
                              void* d_out, int out_size)
{
    const float* x   = (const float*)d_in[0];
    const void*  idx = d_in[1];
    const float* W1  = (const float*)d_in[2];
    const float* b1  = (const float*)d_in[3];
    const float* W2  = (const float*)d_in[4];
    const float* b2  = (const float*)d_in[5];
    float* out = (float*)d_out;

    const int E = in_sizes[1] / 2;

    cudaFuncSetAttribute(node_gemm_kernel,
                         cudaFuncAttributeMaxDynamicSharedMemorySize, SMEM_TOTAL);

    prep_w_kernel<<<128, 256>>>(W1);

    const int n_tiles = (N_NODES + M_TILE - 1) / M_TILE;   // 782
    node_gemm_kernel<<<n_tiles, 512, SMEM_TOTAL>>>(x, b1);

    edge_kernel<<<1184, 256>>>(idx, W2, b2, out, E);
}

// round 5
// speedup vs baseline: 2.4078x; 1.6202x over previous
#include <cuda_runtime.h>
#include <cuda_fp16.h>
#include <cstdint>

#define N_NODES 100000
#define D_FEAT  128
#define HIDDEN  128
#define M_TILE  128
#define KPAD    136          // fp16 row stride (272 B) -> conflict-free fragment loads

// ---------------------------------------------------------------------------
// Global scratch.  A/B stored fp16 (51 MB working set -> L2-resident gathers).
// ---------------------------------------------------------------------------
__device__ __half g_A[N_NODES * HIDDEN];       // x @ W1[:128] + b1
__device__ __half g_B[N_NODES * HIDDEN];       // x @ W1[128:]
__device__ __half g_Wh[256 * KPAD];            // Wfull^T padded, fp16

// ---------------------------------------------------------------------------
// Prep: Wfull[k][n] (256 cols n) -> g_Wh[n][k] fp16.
// ---------------------------------------------------------------------------
__global__ __launch_bounds__(256) void prep_w_kernel(const float* __restrict__ W1)
{
    int i = blockIdx.x * 256 + threadIdx.x;    // n*128 + k
    if (i >= 256 * 128) return;
    int n = i >> 7, k = i & 127;
    int r = (n < 128) ? k : (128 + k);
    int c = (n < 128) ? n : (n - 128);
    g_Wh[n * KPAD + k] = __float2half_rn(W1[r * 128 + c]);
}

// ---------------------------------------------------------------------------
// Stage 1: C[128 nodes][256 cols] per CTA via mma.sync m16n8k16 fp16 (fp32 acc).
// 512 threads, 16 warps in 4x4 grid of 32(M) x 64(N) warp tiles, single pass.
// SMEM: sX [128][KPAD] fp16 (34816 B) + sW [256][KPAD] fp16 (69632 B) = 104448 B
// -> 2 CTAs/SM.
// ---------------------------------------------------------------------------
#define SM_X 0
#define SM_W 34816
#define SMEM_TOTAL 104448

static __device__ __forceinline__ uint32_t smem_u32(const void* p) {
    uint32_t a;
    asm("{ .reg .u64 t; cvta.to.shared.u64 t, %1; cvt.u32.u64 %0, t; }" : "=r"(a) : "l"(p));
    return a;
}

static __device__ __forceinline__ void mma_fp16(
    float c[4], const uint32_t a[4], const uint32_t b[2])
{
    asm volatile(
        "mma.sync.aligned.m16n8k16.row.col.f32.f16.f16.f32 "
        "{%0,%1,%2,%3}, {%4,%5,%6,%7}, {%8,%9}, {%0,%1,%2,%3};"
        : "+f"(c[0]), "+f"(c[1]), "+f"(c[2]), "+f"(c[3])
        : "r"(a[0]), "r"(a[1]), "r"(a[2]), "r"(a[3]), "r"(b[0]), "r"(b[1]));
}

__global__ __launch_bounds__(512) void node_gemm_kernel(
    const float* __restrict__ x,
    const float* __restrict__ b1)
{
    extern __shared__ char smem[];
    __half* sX = (__half*)(smem + SM_X);
    __half* sW = (__half*)(smem + SM_W);

    const int tid     = threadIdx.x;
    const int m_block = blockIdx.x * M_TILE;

    // ---- W copy via cp.async (overlaps with X load+convert)
    {
        const uint32_t sw = smem_u32(sW);
        const char* gw = (const char*)g_Wh;
        #pragma unroll 2
        for (int i = tid * 16; i < 256 * KPAD * 2; i += 512 * 16)
            asm volatile("cp.async.cg.shared.global [%0], [%1], 16;"
                         :: "r"(sw + i), "l"(gw + i));
        asm volatile("cp.async.commit_group;");
    }

    // ---- load X tile (128 x 128 fp32) -> fp16
    for (int i = tid; i < M_TILE * 64; i += 512) {
        int m = i >> 6;
        int k = (i & 63) * 2;
        int gm = m_block + m;
        float2 v = make_float2(0.f, 0.f);
        if (gm < N_NODES) v = *(const float2*)&x[gm * D_FEAT + k];
        *(__half2*)&sX[m * KPAD + k] = __floats2half2_rn(v.x, v.y);
    }
    asm volatile("cp.async.wait_group 0;");
    __syncthreads();

    // ---- warp tiling: 16 warps, each 32(M) x 64(N)
    const int wid  = tid >> 5;
    const int lane = tid & 31;
    const int g    = lane >> 2;
    const int t    = lane & 3;
    const int mrow0 = (wid & 3) * 32;
    const int ncol0 = (wid >> 2) * 64;     // 0,64,128,192

    float acc[2][8][4];
    #pragma unroll
    for (int mt = 0; mt < 2; mt++)
        #pragma unroll
        for (int nt = 0; nt < 8; nt++)
            #pragma unroll
            for (int r = 0; r < 4; r++) acc[mt][nt][r] = 0.f;

    #pragma unroll
    for (int ks = 0; ks < 8; ks++) {
        const int k0 = ks * 16;
        uint32_t a[2][4];
        #pragma unroll
        for (int mt = 0; mt < 2; mt++) {
            const int rb = mrow0 + mt * 16;
            a[mt][0] = *(const uint32_t*)&sX[(rb + g)     * KPAD + k0 + t * 2];
            a[mt][1] = *(const uint32_t*)&sX[(rb + g + 8) * KPAD + k0 + t * 2];
            a[mt][2] = *(const uint32_t*)&sX[(rb + g)     * KPAD + k0 + t * 2 + 8];
            a[mt][3] = *(const uint32_t*)&sX[(rb + g + 8) * KPAD + k0 + t * 2 + 8];
        }
        #pragma unroll
        for (int nt = 0; nt < 8; nt++) {
            const int cb = ncol0 + nt * 8;
            uint32_t b[2];
            b[0] = *(const uint32_t*)&sW[(cb + g) * KPAD + k0 + t * 2];
            b[1] = *(const uint32_t*)&sW[(cb + g) * KPAD + k0 + t * 2 + 8];
            mma_fp16(acc[0][nt], a[0], b);
            mma_fp16(acc[1][nt], a[1], b);
        }
    }

    // ---- epilogue: +b1 (A-half), fp16 store
    const bool isA = (ncol0 < 128);
    __half* halfp = isA ? g_A : g_B;
    const int clocal0 = isA ? ncol0 : (ncol0 - 128);

    float2 bb[8];
    #pragma unroll
    for (int nt = 0; nt < 8; nt++) {
        if (isA) bb[nt] = *(const float2*)&b1[ncol0 + nt * 8 + t * 2];
        else     bb[nt] = make_float2(0.f, 0.f);
    }
    #pragma unroll
    for (int mt = 0; mt < 2; mt++) {
        const int node0 = m_block + mrow0 + mt * 16 + g;
        const int node1 = node0 + 8;
        #pragma unroll
        for (int nt = 0; nt < 8; nt++) {
            const int c = clocal0 + nt * 8 + t * 2;
            if (node0 < N_NODES)
                *(__half2*)&halfp[(size_t)node0 * HIDDEN + c] =
                    __floats2half2_rn(acc[mt][nt][0] + bb[nt].x, acc[mt][nt][1] + bb[nt].y);
            if (node1 < N_NODES)
                *(__half2*)&halfp[(size_t)node1 * HIDDEN + c] =
                    __floats2half2_rn(acc[mt][nt][2] + bb[nt].x, acc[mt][nt][3] + bb[nt].y);
        }
    }
}

// ---------------------------------------------------------------------------
// Stage 2: half-warp per edge, 2 edges per half-warp per iteration (MLP=4
// row-gathers in flight per warp-iter).
// ---------------------------------------------------------------------------
static __device__ __forceinline__ float tanh_fast(float x) {
    float y;
    asm("tanh.approx.f32 %0, %1;" : "=f"(y) : "f"(x));
    return y;
}

__global__ __launch_bounds__(256) void edge_kernel(
    const void*  __restrict__ idx,
    const float* __restrict__ W2,
    const float* __restrict__ b2,
    float*       __restrict__ out,
    int E)
{
    const int lane = threadIdx.x & 31;
    const int hw   = lane >> 4;
    const int hl   = lane & 15;
    const int gwarp = (blockIdx.x * blockDim.x + threadIdx.x) >> 5;
    const int nwarps = (gridDim.x * blockDim.x) >> 5;

    const int* w32 = (const int*)idx;
    const bool is64 = ((w32[1] | w32[3] | w32[5] | w32[7]) == 0);
    const long long* p64 = (const long long*)idx;

    float wv[8];
    {
        float4 w0 = *(const float4*)&W2[hl * 8];
        float4 w1 = *(const float4*)&W2[hl * 8 + 4];
        wv[0] = w0.x; wv[1] = w0.y; wv[2] = w0.z; wv[3] = w0.w;
        wv[4] = w1.x; wv[5] = w1.y; wv[6] = w1.z; wv[7] = w1.w;
    }
    const float bias2 = b2[0];

    const uint4* Au = (const uint4*)g_A;   // 16 uint4 per row
    const uint4* Bu = (const uint4*)g_B;

    const int Q = (E + 3) >> 2;            // quads of edges
    for (int p = gwarp; p < Q; p += nwarps) {
        const int e0 = p * 4 + hw * 2;
        const int e1 = e0 + 1;
        const bool v0 = (e0 < E), v1 = (e1 < E);
        const int c0 = v0 ? e0 : (E - 1);
        const int c1 = v1 ? e1 : (E - 1);

        int s0, d0, s1, d1;
        if (is64) {
            s0 = (int)p64[c0]; d0 = (int)p64[E + c0];
            s1 = (int)p64[c1]; d1 = (int)p64[E + c1];
        } else {
            s0 = w32[c0];      d0 = w32[E + c0];
            s1 = w32[c1];      d1 = w32[E + c1];
        }

        uint4 ua0 = Au[(size_t)s0 * 16 + hl];
        uint4 ub0 = Bu[(size_t)d0 * 16 + hl];
        uint4 ua1 = Au[(size_t)s1 * 16 + hl];
        uint4 ub1 = Bu[(size_t)d1 * 16 + hl];

        float acc0 = 0.f, acc1 = 0.f;
        {
            const uint32_t* pa0 = (const uint32_t*)&ua0;
            const uint32_t* pb0 = (const uint32_t*)&ub0;
            const uint32_t* pa1 = (const uint32_t*)&ua1;
            const uint32_t* pb1 = (const uint32_t*)&ub1;
            #pragma unroll
            for (int q = 0; q < 4; q++) {
                float2 af0 = __half22float2(*(const __half2*)&pa0[q]);
                float2 bf0 = __half22float2(*(const __half2*)&pb0[q]);
                float2 af1 = __half22float2(*(const __half2*)&pa1[q]);
                float2 bf1 = __half22float2(*(const __half2*)&pb1[q]);
                acc0 = fmaf(tanh_fast(af0.x + bf0.x), wv[q * 2],     acc0);
                acc0 = fmaf(tanh_fast(af0.y + bf0.y), wv[q * 2 + 1], acc0);
                acc1 = fmaf(tanh_fast(af1.x + bf1.x), wv[q * 2],     acc1);
                acc1 = fmaf(tanh_fast(af1.y + bf1.y), wv[q * 2 + 1], acc1);
            }
        }

        #pragma unroll
        for (int off = 8; off; off >>= 1) {
            acc0 += __shfl_xor_sync(0xffffffffu, acc0, off);
            acc1 += __shfl_xor_sync(0xffffffffu, acc1, off);
        }

        if (hl == 0) {
            if (v0) out[e0] = __fdividef(1.0f, 1.0f + __expf(-(acc0 + bias2)));
            if (v1) out[e1] = __fdividef(1.0f, 1.0f + __expf(-(acc1 + bias2)));
        }
    }
}

// ---------------------------------------------------------------------------
extern "C" void kernel_launch(void* const* d_in, const int* in_sizes, int n_in,
                              void* d_out, int out_size)
{
    const float* x   = (const float*)d_in[0];
    const void*  idx = d_in[1];
    const float* W1  = (const float*)d_in[2];
    const float* b1  = (const float*)d_in[3];
    const float* W2  = (const float*)d_in[4];
    const float* b2  = (const float*)d_in[5];
    float* out = (float*)d_out;

    const int E = in_sizes[1] / 2;

    cudaFuncSetAttribute(node_gemm_kernel,
                         cudaFuncAttributeMaxDynamicSharedMemorySize, SMEM_TOTAL);

    prep_w_kernel<<<128, 256>>>(W1);

    const int n_tiles = (N_NODES + M_TILE - 1) / M_TILE;   // 782
    node_gemm_kernel<<<n_tiles, 512, SMEM_TOTAL>>>(x, b1);

    edge_kernel<<<1184, 256>>>(idx, W2, b2, out, E);
}